// round 15
// baseline (speedup 1.0000x reference)
#include <cuda_runtime.h>
#include <cuda_fp16.h>
#include <stdint.h>
#include <math.h>

#define N_TOK  32768
#define HID    1024
#define NEXP   64
#define H4     256
#define N_TOT  320          // 64 router + 256 hidden

#define MT      64          // M rows per CTA
#define KC      32
#define NCHUNK  (HID / KC)  // 32
#define THREADS 256

// smem stage: A32 (64 rows x 160B pitch) | B_HI 20480 | B_LO 20480
#define A_PITCH  160
#define B_HI_OFF 10240
#define B_LO_OFF 30720
#define ST_BYTES 51200
#define NSTAGE   4
#define SMEM_TOTAL (NSTAGE * ST_BYTES)   // 204800 -> 1 CTA/SM, 255 regs/thread

// ---------------- device scratch (weights only) ----------------
__device__ __align__(16) __half g_whi[N_TOT * HID];
__device__ __align__(16) __half g_wlo[N_TOT * HID];
__device__ float g_load[NEXP];
__device__ float g_ent;

__device__ __forceinline__ uint32_t smem_u32(const void* p) {
    uint32_t a;
    asm("{ .reg .u64 t; cvta.to.shared.u64 t, %1; cvt.u32.u64 %0, t; }" : "=r"(a) : "l"(p));
    return a;
}
__device__ __forceinline__ void cp16(uint32_t dst, const void* src) {
    asm volatile("cp.async.cg.shared.global [%0], [%1], 16;"
                 :: "r"(dst), "l"(__cvta_generic_to_global(src)));
}
__device__ __forceinline__ void ldsm4(uint32_t* r, uint32_t addr) {
    asm("ldmatrix.sync.aligned.m8n8.x4.shared.b16 {%0,%1,%2,%3}, [%4];"
        : "=r"(r[0]), "=r"(r[1]), "=r"(r[2]), "=r"(r[3]) : "r"(addr) : "memory");
}
__device__ __forceinline__ void mma16816(float* c, const uint32_t* a, const uint32_t* b) {
    asm("mma.sync.aligned.m16n8k16.row.col.f32.f16.f16.f32 "
        "{%0,%1,%2,%3}, {%4,%5,%6,%7}, {%8,%9}, {%0,%1,%2,%3};"
        : "+f"(c[0]), "+f"(c[1]), "+f"(c[2]), "+f"(c[3])
        : "r"(a[0]), "r"(a[1]), "r"(a[2]), "r"(a[3]), "r"(b[0]), "r"(b[1]));
}
__device__ __forceinline__ uint32_t h2u(__half2 h) {
    uint32_t u; __builtin_memcpy(&u, &h, 4); return u;
}
__device__ __forceinline__ void cvt_pair(float x, float y, uint32_t& hi, uint32_t& lo) {
    __half2 h = __floats2half2_rn(x, y);
    float2 g = __half22float2(h);
    __half2 l = __floats2half2_rn(x - g.x, y - g.y);
    hi = h2u(h); lo = h2u(l);
}
__device__ __forceinline__ float2 lds64(const char* smem, uint32_t off) {
    return *reinterpret_cast<const float2*>(smem + off);
}

// ---------------- prep: weights -> fp16 hi/lo + stat init ----------------
#define W_UNITS (N_TOT * HID / 8)   // 40960
#define W_BLOCKS (W_UNITS / 256)    // 160

__global__ void prep_w_kernel(const float* __restrict__ RW, const float* __restrict__ W1) {
    if (blockIdx.x == 0 && threadIdx.x < NEXP) {
        g_load[threadIdx.x] = 0.0f;
        if (threadIdx.x == 0) g_ent = 0.0f;
    }
    size_t u = (size_t)blockIdx.x * 256 + threadIdx.x;
    size_t e = u * 8;
    int row = (int)(e >> 10);
    const float* src = (row < NEXP) ? (RW + e) : (W1 + e - (size_t)NEXP * HID);
    float4 f0 = reinterpret_cast<const float4*>(src)[0];
    float4 f1 = reinterpret_cast<const float4*>(src)[1];
    uint32_t h0, l0, h1, l1, h2, l2, h3, l3;
    cvt_pair(f0.x, f0.y, h0, l0);
    cvt_pair(f0.z, f0.w, h1, l1);
    cvt_pair(f1.x, f1.y, h2, l2);
    cvt_pair(f1.z, f1.w, h3, l3);
    *reinterpret_cast<uint4*>(g_whi + e) = make_uint4(h0, h1, h2, h3);
    *reinterpret_cast<uint4*>(g_wlo + e) = make_uint4(l0, l1, l2, l3);
}

// ---------------- GEMM (occ 1, high regs) + fused router epilogue ----------------
__global__ void __launch_bounds__(THREADS, 1)
gemm_kernel(const float* __restrict__ X,
            const float* __restrict__ B1, const float* __restrict__ W2,
            const float* __restrict__ B2,
            float* __restrict__ logits, float* __restrict__ sel, float* __restrict__ wts)
{
    extern __shared__ __align__(1024) char smem[];
    const uint32_t sbase = smem_u32(smem);
    const int tid = threadIdx.x;
    const int lane = tid & 31;
    const int wid = tid >> 5;
    const int wm = wid & 1;          // 2 m-groups * 32 rows
    const int wn = wid >> 1;         // 4 n-groups * 80 cols
    const int m0 = blockIdx.x * MT;

    float acc[2][10][4];
#pragma unroll
    for (int i = 0; i < 2; i++)
#pragma unroll
        for (int j = 0; j < 10; j++)
#pragma unroll
            for (int r = 0; r < 4; r++) acc[i][j][r] = 0.0f;

    uint32_t aL[2];
#pragma unroll
    for (int mt = 0; mt < 2; mt++) {
        int arow = wm * 32 + mt * 16 + (lane >> 2);
        aL[mt] = (uint32_t)arow * A_PITCH + (uint32_t)(lane & 3) * 8;
    }

    uint32_t bOff[5], bXor[5];
#pragma unroll
    for (int p = 0; p < 5; p++) {
        int n = wn * 80 + (p * 2 + ((lane >> 4) & 1)) * 8 + (lane & 7);
        bOff[p] = (uint32_t)n * 64;
        bXor[p] = ((uint32_t)n * 8) & 0x30;
    }
    const uint32_t bKB = ((lane >> 3) & 1) * 16;

    // chunk issue: A32 512 units + B 2560 units = 3072, 12 per thread
    auto issue = [&](int c) {
        if (c < NCHUNK) {
            const uint32_t sb = sbase + (uint32_t)(c & 3) * ST_BYTES;
            const size_t k0 = (size_t)c * KC;
#pragma unroll
            for (int it = 0; it < 12; it++) {
                int u = tid + it * THREADS;
                if (u < 512) {
                    int r = u >> 3, g = u & 7;
                    const float* src = X + (size_t)(m0 + r) * HID + k0 + g * 4;
                    cp16(sb + (uint32_t)r * A_PITCH + (uint32_t)g * 16, src);
                } else {
                    int t = u - 512;
                    int v = t >= 1280;
                    int j = v ? t - 1280 : t;
                    int n = j >> 2, g = j & 3;
                    const __half* src = (v ? g_wlo : g_whi) + (size_t)n * HID + k0 + g * 8;
                    cp16(sb + (v ? B_LO_OFF : B_HI_OFF) +
                         ((uint32_t)n * 64 + (((uint32_t)g * 16) ^ (((uint32_t)n * 8) & 0x30))),
                         src);
                }
            }
        }
        asm volatile("cp.async.commit_group;");
    };

    // prologue: 3 chunks in flight (R7-proven 1-barrier shape)
    issue(0); issue(1); issue(2);

    for (int c = 0; c < NCHUNK; c++) {
        asm volatile("cp.async.wait_group 2;");   // drain group c
        __syncthreads();                          // data(c) visible; stage (c-1)&3 readers done
        issue(c + 3);                             // overwrites stage (c-1)&3 — safe

        const uint32_t stOff = (uint32_t)(c & 3) * ST_BYTES;
        const char* sA = smem + stOff;
        const uint32_t sb = sbase + stOff;
#pragma unroll
        for (int ks = 0; ks < 2; ks++) {
            const uint32_t kf = ks * 64;
            const uint32_t kb = ks * 32;
            uint32_t ah[2][4], al[2][4], bh[5][4], bl[5][4];
            // assemble A frags (hi + lo) from fp32 smem
#pragma unroll
            for (int mt = 0; mt < 2; mt++) {
                uint32_t base = aL[mt] + kf;
                float2 f00 = lds64(sA, base);
                float2 f10 = lds64(sA, base + 8 * A_PITCH);
                float2 f01 = lds64(sA, base + 32);
                float2 f11 = lds64(sA, base + 8 * A_PITCH + 32);
                cvt_pair(f00.x, f00.y, ah[mt][0], al[mt][0]);
                cvt_pair(f10.x, f10.y, ah[mt][1], al[mt][1]);
                cvt_pair(f01.x, f01.y, ah[mt][2], al[mt][2]);
                cvt_pair(f11.x, f11.y, ah[mt][3], al[mt][3]);
            }
            // B frags: hi and lo in SEPARATE buffers (no forced reuse; regs ample at occ 1)
#pragma unroll
            for (int p = 0; p < 5; p++)
                ldsm4(bh[p], sb + B_HI_OFF + bOff[p] + ((kb + bKB) ^ bXor[p]));
#pragma unroll
            for (int p = 0; p < 5; p++)
                ldsm4(bl[p], sb + B_LO_OFF + bOff[p] + ((kb + bKB) ^ bXor[p]));
            // pass 1: ah x bh
#pragma unroll
            for (int mt = 0; mt < 2; mt++)
#pragma unroll
                for (int p = 0; p < 5; p++) {
                    mma16816(acc[mt][p * 2 + 0], ah[mt], &bh[p][0]);
                    mma16816(acc[mt][p * 2 + 1], ah[mt], &bh[p][2]);
                }
            // pass 2: al x bh
#pragma unroll
            for (int mt = 0; mt < 2; mt++)
#pragma unroll
                for (int p = 0; p < 5; p++) {
                    mma16816(acc[mt][p * 2 + 0], al[mt], &bh[p][0]);
                    mma16816(acc[mt][p * 2 + 1], al[mt], &bh[p][2]);
                }
            // pass 3: ah x bl
#pragma unroll
            for (int mt = 0; mt < 2; mt++)
#pragma unroll
                for (int p = 0; p < 5; p++) {
                    mma16816(acc[mt][p * 2 + 0], ah[mt], &bl[p][0]);
                    mma16816(acc[mt][p * 2 + 1], ah[mt], &bl[p][2]);
                }
        }
    }

    // ---------------- fused epilogue ----------------
    float* s_log  = reinterpret_cast<float*>(smem);           // [64][68] = 17408 B
    float* s_u    = reinterpret_cast<float*>(smem + 17408);   // [64]
    float* s_load = s_u + 64;                                 // [64]
    float* s_ent  = s_load + NEXP;

    __syncthreads();
    if (tid < MT)   s_u[tid] = B2[0];
    if (tid < NEXP) s_load[tid] = 0.0f;
    if (tid == 0)   *s_ent = 0.0f;
    __syncthreads();

#pragma unroll
    for (int mt = 0; mt < 2; mt++) {
        float u0 = 0.0f, u1 = 0.0f;
        const int row0 = wm * 32 + mt * 16 + (lane >> 2);
#pragma unroll
        for (int nt = 0; nt < 10; nt++) {
            const int nb = wn * 80 + nt * 8 + (lane & 3) * 2;
            const bool is_logit = (wn == 0 && nt < 8);
#pragma unroll
            for (int r = 0; r < 4; r++) {
                const int n = nb + (r & 1);
                const float v = acc[mt][nt][r];
                if (is_logit) {
                    const int rl = row0 + ((r >= 2) ? 8 : 0);
                    s_log[rl * 68 + n] = v;
                } else {
                    const int h = n - 64;
                    const float hh = fmaxf(v + __ldg(B1 + h), 0.0f) * __ldg(W2 + h);
                    if (r < 2) u0 += hh; else u1 += hh;
                }
            }
        }
        u0 += __shfl_xor_sync(0xffffffffu, u0, 1);
        u0 += __shfl_xor_sync(0xffffffffu, u0, 2);
        u1 += __shfl_xor_sync(0xffffffffu, u1, 1);
        u1 += __shfl_xor_sync(0xffffffffu, u1, 2);
        if ((lane & 3) == 0) {
            atomicAdd(&s_u[row0], u0);
            atomicAdd(&s_u[row0 + 8], u1);
        }
    }
    __syncthreads();

    // logits -> global: 64 rows x 16 float4 = 1024 units
#pragma unroll
    for (int it = 0; it < 4; it++) {
        int t = tid + it * THREADS;
        int r = t >> 4, c4 = t & 15;
        float4 v = *reinterpret_cast<const float4*>(s_log + r * 68 + c4 * 4);
        *reinterpret_cast<float4*>(logits + (size_t)(m0 + r) * NEXP + c4 * 4) = v;
    }

    // softmax stats: 4 lanes per token x 16 experts (64 tokens x 4 = 256 threads)
    {
        const int t = tid >> 2, q = tid & 3;
        const float* row = s_log + t * 68 + q * 16;
        float xs[16];
        float mx = -INFINITY;
#pragma unroll
        for (int i = 0; i < 16; i++) { xs[i] = row[i]; mx = fmaxf(mx, xs[i]); }
        mx = fmaxf(mx, __shfl_xor_sync(0xffffffffu, mx, 1));
        mx = fmaxf(mx, __shfl_xor_sync(0xffffffffu, mx, 2));
        float se = 0.0f, sc = 0.0f;
#pragma unroll
        for (int i = 0; i < 16; i++) {
            float d = xs[i] - mx;
            float e = __expf(d);
            se += e;
            sc = fmaf(e, d, sc);
            xs[i] = e;
        }
        se += __shfl_xor_sync(0xffffffffu, se, 1);
        se += __shfl_xor_sync(0xffffffffu, se, 2);
        sc += __shfl_xor_sync(0xffffffffu, sc, 1);
        sc += __shfl_xor_sync(0xffffffffu, sc, 2);
        const float inv = 1.0f / se;
#pragma unroll
        for (int i = 0; i < 16; i++) {
            float p = xs[i] * inv;
            p += __shfl_xor_sync(0xffffffffu, p, 4);
            p += __shfl_xor_sync(0xffffffffu, p, 8);
            p += __shfl_xor_sync(0xffffffffu, p, 16);
            xs[i] = p;
        }
        if (lane < 4) {
#pragma unroll
            for (int i = 0; i < 16; i++) atomicAdd(&s_load[lane * 16 + i], xs[i]);
        }
        float ent = (q == 0) ? (__logf(se) - sc * inv) : 0.0f;
        ent += __shfl_xor_sync(0xffffffffu, ent, 1);
        ent += __shfl_xor_sync(0xffffffffu, ent, 2);
        ent += __shfl_xor_sync(0xffffffffu, ent, 4);
        ent += __shfl_xor_sync(0xffffffffu, ent, 8);
        ent += __shfl_xor_sync(0xffffffffu, ent, 16);
        if (lane == 0) atomicAdd(s_ent, ent);
    }
    __syncthreads();

    // top-k + weights (tid<64); stats flush (tid in [64,129))
    if (tid < MT) {
        const int m = m0 + tid;
        const float* row = s_log + tid * 68;

        float v0 = -INFINITY, v1 = -INFINITY, v2 = -INFINITY, v3 = -INFINITY;
        int i0 = 0, i1 = 0, i2 = 0, i3 = 0;
#pragma unroll
        for (int j = 0; j < NEXP; j++) {
            float x = row[j];
            if (x > v3) {
                if (x > v0)      { v3=v2;i3=i2; v2=v1;i2=i1; v1=v0;i1=i0; v0=x;i0=j; }
                else if (x > v1) { v3=v2;i3=i2; v2=v1;i2=i1; v1=x;i1=j; }
                else if (x > v2) { v3=v2;i3=i2; v2=x;i2=j; }
                else             { v3=x;i3=j; }
            }
        }
        float u = s_u[tid];
        float cplx = 1.0f / (1.0f + expf(-u));
        int kk = (cplx > 0.5f) ? 4 : 1;
        float e0 = 1.0f;
        float e1 = (kk > 1) ? expf(v1 - v0) : 0.0f;
        float e2 = (kk > 2) ? expf(v2 - v0) : 0.0f;
        float e3 = (kk > 3) ? expf(v3 - v0) : 0.0f;
        float wi = 1.0f / (e0 + e1 + e2 + e3);

        *reinterpret_cast<float4*>(sel + (size_t)m * 4) =
            make_float4((float)i0, (float)((kk > 1) ? i1 : 0),
                        (float)((kk > 2) ? i2 : 0), (float)((kk > 3) ? i3 : 0));
        *reinterpret_cast<float4*>(wts + (size_t)m * 4) =
            make_float4(e0 * wi, e1 * wi, e2 * wi, e3 * wi);
    } else if (tid < MT + NEXP) {
        atomicAdd(&g_load[tid - MT], s_load[tid - MT]);
    } else if (tid == MT + NEXP) {
        atomicAdd(&g_ent, *s_ent);
    }
}

// ---------------- finalize ----------------
__global__ void finalize_kernel(float* __restrict__ out_var, float* __restrict__ out_ent) {
    if (threadIdx.x == 0) {
        float xs[NEXP];
        float mean = 0.0f;
        for (int e = 0; e < NEXP; e++) { xs[e] = g_load[e] * (1.0f / N_TOK); mean += xs[e]; }
        mean *= (1.0f / NEXP);
        float var = 0.0f;
        for (int e = 0; e < NEXP; e++) { float d = xs[e] - mean; var += d * d; }
        out_var[0] = var * (1.0f / (NEXP - 1));
        out_ent[0] = g_ent * (1.0f / N_TOK);
    }
}

// ---------------- launch ----------------
extern "C" void kernel_launch(void* const* d_in, const int* in_sizes, int n_in,
                              void* d_out, int out_size) {
    const float* X  = (const float*)d_in[0];
    const float* RW = (const float*)d_in[1];
    const float* W1 = (const float*)d_in[2];
    const float* B1 = (const float*)d_in[3];
    const float* W2 = (const float*)d_in[4];
    const float* B2 = (const float*)d_in[5];

    float* out    = (float*)d_out;
    float* logits = out;
    float* sel    = logits + (size_t)N_TOK * NEXP;
    float* wts    = sel + (size_t)N_TOK * 4;
    float* ovar   = wts + (size_t)N_TOK * 4;
    float* oent   = ovar + 1;

    cudaFuncSetAttribute(gemm_kernel, cudaFuncAttributeMaxDynamicSharedMemorySize, SMEM_TOTAL);

    prep_w_kernel<<<W_BLOCKS, 256>>>(RW, W1);
    gemm_kernel<<<N_TOK / MT, THREADS, SMEM_TOTAL>>>(X, B1, W2, B2, logits, sel, wts);
    finalize_kernel<<<1, 32>>>(ovar, oent);
}

// round 16
// speedup vs baseline: 1.1543x; 1.1543x over previous
#include <cuda_runtime.h>
#include <cuda_fp16.h>
#include <stdint.h>
#include <math.h>

#define N_TOK  32768
#define HID    1024
#define NEXP   64
#define H4     256
#define N_TOT  320          // 64 router + 256 hidden

#define MT      64          // M rows per CTA (2 CTAs/SM)
#define KC      32
#define NCHUNK  (HID / KC)  // 32
#define THREADS 256

// smem stage: A32 (64 rows x 160B pitch) | B_HI 20480 | B_LO 20480
#define A_PITCH  160
#define B_HI_OFF 10240
#define B_LO_OFF 30720
#define ST_BYTES 51200
#define SMEM_TOTAL (2 * ST_BYTES)   // 102400 -> 2 CTAs/SM

// ---------------- device scratch (weights only) ----------------
__device__ __align__(16) __half g_whi[N_TOT * HID];
__device__ __align__(16) __half g_wlo[N_TOT * HID];
__device__ float g_load[NEXP];
__device__ float g_ent;

__device__ __forceinline__ uint32_t smem_u32(const void* p) {
    uint32_t a;
    asm("{ .reg .u64 t; cvta.to.shared.u64 t, %1; cvt.u32.u64 %0, t; }" : "=r"(a) : "l"(p));
    return a;
}
__device__ __forceinline__ void cp16(uint32_t dst, const void* src) {
    asm volatile("cp.async.cg.shared.global [%0], [%1], 16;"
                 :: "r"(dst), "l"(__cvta_generic_to_global(src)));
}
__device__ __forceinline__ void ldsm4(uint32_t* r, uint32_t addr) {
    asm("ldmatrix.sync.aligned.m8n8.x4.shared.b16 {%0,%1,%2,%3}, [%4];"
        : "=r"(r[0]), "=r"(r[1]), "=r"(r[2]), "=r"(r[3]) : "r"(addr) : "memory");
}
__device__ __forceinline__ void mma16816(float* c, const uint32_t* a, const uint32_t* b) {
    asm("mma.sync.aligned.m16n8k16.row.col.f32.f16.f16.f32 "
        "{%0,%1,%2,%3}, {%4,%5,%6,%7}, {%8,%9}, {%0,%1,%2,%3};"
        : "+f"(c[0]), "+f"(c[1]), "+f"(c[2]), "+f"(c[3])
        : "r"(a[0]), "r"(a[1]), "r"(a[2]), "r"(a[3]), "r"(b[0]), "r"(b[1]));
}
__device__ __forceinline__ uint32_t h2u(__half2 h) {
    uint32_t u; __builtin_memcpy(&u, &h, 4); return u;
}
__device__ __forceinline__ void cvt_pair(float x, float y, uint32_t& hi, uint32_t& lo) {
    __half2 h = __floats2half2_rn(x, y);
    float2 g = __half22float2(h);
    __half2 l = __floats2half2_rn(x - g.x, y - g.y);
    hi = h2u(h); lo = h2u(l);
}
__device__ __forceinline__ float2 lds64(const char* smem, uint32_t off) {
    return *reinterpret_cast<const float2*>(smem + off);
}

// ---------------- prep: weights -> fp16 hi/lo + stat init ----------------
#define W_UNITS (N_TOT * HID / 8)   // 40960
#define W_BLOCKS (W_UNITS / 256)    // 160

__global__ void prep_w_kernel(const float* __restrict__ RW, const float* __restrict__ W1) {
    if (blockIdx.x == 0 && threadIdx.x < NEXP) {
        g_load[threadIdx.x] = 0.0f;
        if (threadIdx.x == 0) g_ent = 0.0f;
    }
    size_t u = (size_t)blockIdx.x * 256 + threadIdx.x;
    size_t e = u * 8;
    int row = (int)(e >> 10);
    const float* src = (row < NEXP) ? (RW + e) : (W1 + e - (size_t)NEXP * HID);
    float4 f0 = reinterpret_cast<const float4*>(src)[0];
    float4 f1 = reinterpret_cast<const float4*>(src)[1];
    uint32_t h0, l0, h1, l1, h2, l2, h3, l3;
    cvt_pair(f0.x, f0.y, h0, l0);
    cvt_pair(f0.z, f0.w, h1, l1);
    cvt_pair(f1.x, f1.y, h2, l2);
    cvt_pair(f1.z, f1.w, h3, l3);
    *reinterpret_cast<uint4*>(g_whi + e) = make_uint4(h0, h1, h2, h3);
    *reinterpret_cast<uint4*>(g_wlo + e) = make_uint4(l0, l1, l2, l3);
}

// ---------------- GEMM (occ 2, 1-barrier loop) + fused router epilogue ----------------
__global__ void __launch_bounds__(THREADS, 2)
gemm_kernel(const float* __restrict__ X,
            const float* __restrict__ B1, const float* __restrict__ W2,
            const float* __restrict__ B2,
            float* __restrict__ logits, float* __restrict__ sel, float* __restrict__ wts)
{
    extern __shared__ __align__(1024) char smem[];
    const uint32_t sbase = smem_u32(smem);
    const int tid = threadIdx.x;
    const int lane = tid & 31;
    const int wid = tid >> 5;
    const int wm = wid & 1;          // 2 m-groups * 32 rows
    const int wn = wid >> 1;         // 4 n-groups * 80 cols
    const int m0 = blockIdx.x * MT;

    float acc[2][10][4];
#pragma unroll
    for (int i = 0; i < 2; i++)
#pragma unroll
        for (int j = 0; j < 10; j++)
#pragma unroll
            for (int r = 0; r < 4; r++) acc[i][j][r] = 0.0f;

    uint32_t aL[2];
#pragma unroll
    for (int mt = 0; mt < 2; mt++) {
        int arow = wm * 32 + mt * 16 + (lane >> 2);
        aL[mt] = (uint32_t)arow * A_PITCH + (uint32_t)(lane & 3) * 8;
    }

    uint32_t bOff[5], bXor[5];
#pragma unroll
    for (int p = 0; p < 5; p++) {
        int n = wn * 80 + (p * 2 + ((lane >> 4) & 1)) * 8 + (lane & 7);
        bOff[p] = (uint32_t)n * 64;
        bXor[p] = ((uint32_t)n * 8) & 0x30;
    }
    const uint32_t bKB = ((lane >> 3) & 1) * 16;

    // chunk issue: A32 512 units + B 2560 units = 3072, 12 per thread
    auto issue = [&](int c) {
        if (c < NCHUNK) {
            const uint32_t sb = sbase + (uint32_t)(c & 1) * ST_BYTES;
            const size_t k0 = (size_t)c * KC;
#pragma unroll
            for (int it = 0; it < 12; it++) {
                int u = tid + it * THREADS;
                if (u < 512) {
                    int r = u >> 3, g = u & 7;
                    const float* src = X + (size_t)(m0 + r) * HID + k0 + g * 4;
                    cp16(sb + (uint32_t)r * A_PITCH + (uint32_t)g * 16, src);
                } else {
                    int t = u - 512;
                    int v = t >= 1280;
                    int j = v ? t - 1280 : t;
                    int n = j >> 2, g = j & 3;
                    const __half* src = (v ? g_wlo : g_whi) + (size_t)n * HID + k0 + g * 8;
                    cp16(sb + (v ? B_LO_OFF : B_HI_OFF) +
                         ((uint32_t)n * 64 + (((uint32_t)g * 16) ^ (((uint32_t)n * 8) & 0x30))),
                         src);
                }
            }
        }
        asm volatile("cp.async.commit_group;");
    };

    issue(0);

    for (int c = 0; c < NCHUNK; c++) {
        asm volatile("cp.async.wait_group 0;");   // chunk c landed
        __syncthreads();                          // visible to all; compute(c-1) readers done
        issue(c + 1);                             // overwrites stage (c-1)&1 — safe now

        const uint32_t stOff = (uint32_t)(c & 1) * ST_BYTES;
        const char* sA = smem + stOff;
        const uint32_t sb = sbase + stOff;
#pragma unroll
        for (int ks = 0; ks < 2; ks++) {
            const uint32_t kf = ks * 64;
            const uint32_t kb = ks * 32;
            uint32_t ah[2][4], al[2][4], bb[5][4];
            // assemble A frags (hi + lo) from fp32 smem
#pragma unroll
            for (int mt = 0; mt < 2; mt++) {
                uint32_t base = aL[mt] + kf;
                float2 f00 = lds64(sA, base);
                float2 f10 = lds64(sA, base + 8 * A_PITCH);
                float2 f01 = lds64(sA, base + 32);
                float2 f11 = lds64(sA, base + 8 * A_PITCH + 32);
                cvt_pair(f00.x, f00.y, ah[mt][0], al[mt][0]);
                cvt_pair(f10.x, f10.y, ah[mt][1], al[mt][1]);
                cvt_pair(f01.x, f01.y, ah[mt][2], al[mt][2]);
                cvt_pair(f11.x, f11.y, ah[mt][3], al[mt][3]);
            }
#pragma unroll
            for (int p = 0; p < 5; p++)
                ldsm4(bb[p], sb + B_HI_OFF + bOff[p] + ((kb + bKB) ^ bXor[p]));
            // pass 1: ah x bh
#pragma unroll
            for (int mt = 0; mt < 2; mt++)
#pragma unroll
                for (int p = 0; p < 5; p++) {
                    mma16816(acc[mt][p * 2 + 0], ah[mt], &bb[p][0]);
                    mma16816(acc[mt][p * 2 + 1], ah[mt], &bb[p][2]);
                }
            // pass 2: al x bh
#pragma unroll
            for (int mt = 0; mt < 2; mt++)
#pragma unroll
                for (int p = 0; p < 5; p++) {
                    mma16816(acc[mt][p * 2 + 0], al[mt], &bb[p][0]);
                    mma16816(acc[mt][p * 2 + 1], al[mt], &bb[p][2]);
                }
            // bl (overwrite bb)
#pragma unroll
            for (int p = 0; p < 5; p++)
                ldsm4(bb[p], sb + B_LO_OFF + bOff[p] + ((kb + bKB) ^ bXor[p]));
            // pass 3: ah x bl
#pragma unroll
            for (int mt = 0; mt < 2; mt++)
#pragma unroll
                for (int p = 0; p < 5; p++) {
                    mma16816(acc[mt][p * 2 + 0], ah[mt], &bb[p][0]);
                    mma16816(acc[mt][p * 2 + 1], ah[mt], &bb[p][2]);
                }
        }
    }

    // ---------------- fused epilogue ----------------
    float* s_log  = reinterpret_cast<float*>(smem);           // [64][68] = 17408 B
    float* s_u    = reinterpret_cast<float*>(smem + 17408);   // [64]
    float* s_load = s_u + 64;                                 // [64]
    float* s_ent  = s_load + NEXP;

    __syncthreads();   // all compute done before s_log overwrites stage 0
    if (tid < MT)   s_u[tid] = B2[0];
    if (tid < NEXP) s_load[tid] = 0.0f;
    if (tid == 0)   *s_ent = 0.0f;
    __syncthreads();

#pragma unroll
    for (int mt = 0; mt < 2; mt++) {
        float u0 = 0.0f, u1 = 0.0f;
        const int row0 = wm * 32 + mt * 16 + (lane >> 2);
#pragma unroll
        for (int nt = 0; nt < 10; nt++) {
            const int nb = wn * 80 + nt * 8 + (lane & 3) * 2;
            const bool is_logit = (wn == 0 && nt < 8);
#pragma unroll
            for (int r = 0; r < 4; r++) {
                const int n = nb + (r & 1);
                const float v = acc[mt][nt][r];
                if (is_logit) {
                    const int rl = row0 + ((r >= 2) ? 8 : 0);
                    s_log[rl * 68 + n] = v;
                } else {
                    const int h = n - 64;
                    const float hh = fmaxf(v + __ldg(B1 + h), 0.0f) * __ldg(W2 + h);
                    if (r < 2) u0 += hh; else u1 += hh;
                }
            }
        }
        u0 += __shfl_xor_sync(0xffffffffu, u0, 1);
        u0 += __shfl_xor_sync(0xffffffffu, u0, 2);
        u1 += __shfl_xor_sync(0xffffffffu, u1, 1);
        u1 += __shfl_xor_sync(0xffffffffu, u1, 2);
        if ((lane & 3) == 0) {
            atomicAdd(&s_u[row0], u0);
            atomicAdd(&s_u[row0 + 8], u1);
        }
    }
    __syncthreads();

    // logits -> global: 64 rows x 16 float4 = 1024 units
#pragma unroll
    for (int it = 0; it < 4; it++) {
        int t = tid + it * THREADS;
        int r = t >> 4, c4 = t & 15;
        float4 v = *reinterpret_cast<const float4*>(s_log + r * 68 + c4 * 4);
        *reinterpret_cast<float4*>(logits + (size_t)(m0 + r) * NEXP + c4 * 4) = v;
    }

    // softmax stats: 4 lanes per token x 16 experts (64 tokens x 4 = 256 threads)
    {
        const int t = tid >> 2, q = tid & 3;
        const float* row = s_log + t * 68 + q * 16;
        float xs[16];
        float mx = -INFINITY;
#pragma unroll
        for (int i = 0; i < 16; i++) { xs[i] = row[i]; mx = fmaxf(mx, xs[i]); }
        mx = fmaxf(mx, __shfl_xor_sync(0xffffffffu, mx, 1));
        mx = fmaxf(mx, __shfl_xor_sync(0xffffffffu, mx, 2));
        float se = 0.0f, sc = 0.0f;
#pragma unroll
        for (int i = 0; i < 16; i++) {
            float d = xs[i] - mx;
            float e = __expf(d);
            se += e;
            sc = fmaf(e, d, sc);
            xs[i] = e;
        }
        se += __shfl_xor_sync(0xffffffffu, se, 1);
        se += __shfl_xor_sync(0xffffffffu, se, 2);
        sc += __shfl_xor_sync(0xffffffffu, sc, 1);
        sc += __shfl_xor_sync(0xffffffffu, sc, 2);
        const float inv = 1.0f / se;
#pragma unroll
        for (int i = 0; i < 16; i++) {
            float p = xs[i] * inv;
            p += __shfl_xor_sync(0xffffffffu, p, 4);
            p += __shfl_xor_sync(0xffffffffu, p, 8);
            p += __shfl_xor_sync(0xffffffffu, p, 16);
            xs[i] = p;
        }
        if (lane < 4) {
#pragma unroll
            for (int i = 0; i < 16; i++) atomicAdd(&s_load[lane * 16 + i], xs[i]);
        }
        float ent = (q == 0) ? (__logf(se) - sc * inv) : 0.0f;
        ent += __shfl_xor_sync(0xffffffffu, ent, 1);
        ent += __shfl_xor_sync(0xffffffffu, ent, 2);
        ent += __shfl_xor_sync(0xffffffffu, ent, 4);
        ent += __shfl_xor_sync(0xffffffffu, ent, 8);
        ent += __shfl_xor_sync(0xffffffffu, ent, 16);
        if (lane == 0) atomicAdd(s_ent, ent);
    }
    __syncthreads();

    // top-k + weights (tid<64); stats flush (tid in [64,129))
    if (tid < MT) {
        const int m = m0 + tid;
        const float* row = s_log + tid * 68;

        float v0 = -INFINITY, v1 = -INFINITY, v2 = -INFINITY, v3 = -INFINITY;
        int i0 = 0, i1 = 0, i2 = 0, i3 = 0;
#pragma unroll
        for (int j = 0; j < NEXP; j++) {
            float x = row[j];
            if (x > v3) {
                if (x > v0)      { v3=v2;i3=i2; v2=v1;i2=i1; v1=v0;i1=i0; v0=x;i0=j; }
                else if (x > v1) { v3=v2;i3=i2; v2=v1;i2=i1; v1=x;i1=j; }
                else if (x > v2) { v3=v2;i3=i2; v2=x;i2=j; }
                else             { v3=x;i3=j; }
            }
        }
        float u = s_u[tid];
        float cplx = 1.0f / (1.0f + expf(-u));
        int kk = (cplx > 0.5f) ? 4 : 1;
        float e0 = 1.0f;
        float e1 = (kk > 1) ? expf(v1 - v0) : 0.0f;
        float e2 = (kk > 2) ? expf(v2 - v0) : 0.0f;
        float e3 = (kk > 3) ? expf(v3 - v0) : 0.0f;
        float wi = 1.0f / (e0 + e1 + e2 + e3);

        *reinterpret_cast<float4*>(sel + (size_t)m * 4) =
            make_float4((float)i0, (float)((kk > 1) ? i1 : 0),
                        (float)((kk > 2) ? i2 : 0), (float)((kk > 3) ? i3 : 0));
        *reinterpret_cast<float4*>(wts + (size_t)m * 4) =
            make_float4(e0 * wi, e1 * wi, e2 * wi, e3 * wi);
    } else if (tid < MT + NEXP) {
        atomicAdd(&g_load[tid - MT], s_load[tid - MT]);
    } else if (tid == MT + NEXP) {
        atomicAdd(&g_ent, *s_ent);
    }
}

// ---------------- finalize ----------------
__global__ void finalize_kernel(float* __restrict__ out_var, float* __restrict__ out_ent) {
    if (threadIdx.x == 0) {
        float xs[NEXP];
        float mean = 0.0f;
        for (int e = 0; e < NEXP; e++) { xs[e] = g_load[e] * (1.0f / N_TOK); mean += xs[e]; }
        mean *= (1.0f / NEXP);
        float var = 0.0f;
        for (int e = 0; e < NEXP; e++) { float d = xs[e] - mean; var += d * d; }
        out_var[0] = var * (1.0f / (NEXP - 1));
        out_ent[0] = g_ent * (1.0f / N_TOK);
    }
}

// ---------------- launch ----------------
extern "C" void kernel_launch(void* const* d_in, const int* in_sizes, int n_in,
                              void* d_out, int out_size) {
    const float* X  = (const float*)d_in[0];
    const float* RW = (const float*)d_in[1];
    const float* W1 = (const float*)d_in[2];
    const float* B1 = (const float*)d_in[3];
    const float* W2 = (const float*)d_in[4];
    const float* B2 = (const float*)d_in[5];

    float* out    = (float*)d_out;
    float* logits = out;
    float* sel    = logits + (size_t)N_TOK * NEXP;
    float* wts    = sel + (size_t)N_TOK * 4;
    float* ovar   = wts + (size_t)N_TOK * 4;
    float* oent   = ovar + 1;

    cudaFuncSetAttribute(gemm_kernel, cudaFuncAttributeMaxDynamicSharedMemorySize, SMEM_TOTAL);

    prep_w_kernel<<<W_BLOCKS, 256>>>(RW, W1);
    gemm_kernel<<<N_TOK / MT, THREADS, SMEM_TOTAL>>>(X, B1, W2, B2, logits, sel, wts);
    finalize_kernel<<<1, 32>>>(ovar, oent);
}

// round 17
// speedup vs baseline: 1.1549x; 1.0005x over previous
#include <cuda_runtime.h>
#include <cuda_fp16.h>
#include <stdint.h>
#include <math.h>

#define N_TOK  32768
#define HID    1024
#define NEXP   64
#define H4     256
#define N_TOT  320          // 64 router + 256 hidden

#define MT      64          // M rows per CTA (2 CTAs/SM)
#define KC      32
#define NCHUNK  (HID / KC)  // 32
#define THREADS 256
#define NCTAS   (N_TOK / MT)   // 512

// smem stage: A32 (64 rows x 160B pitch) | B_HI 20480 | B_LO 20480
#define A_PITCH  160
#define B_HI_OFF 10240
#define B_LO_OFF 30720
#define ST_BYTES 51200
#define SMEM_TOTAL (2 * ST_BYTES)   // 102400 -> 2 CTAs/SM

// ---------------- device scratch ----------------
__device__ __align__(16) __half g_whi[N_TOT * HID];
__device__ __align__(16) __half g_wlo[N_TOT * HID];
__device__ float g_load[NEXP];
__device__ float g_ent;
__device__ int   g_ticket = 0;   // self-resetting each launch

__device__ __forceinline__ uint32_t smem_u32(const void* p) {
    uint32_t a;
    asm("{ .reg .u64 t; cvta.to.shared.u64 t, %1; cvt.u32.u64 %0, t; }" : "=r"(a) : "l"(p));
    return a;
}
__device__ __forceinline__ void cp16(uint32_t dst, const void* src) {
    asm volatile("cp.async.cg.shared.global [%0], [%1], 16;"
                 :: "r"(dst), "l"(__cvta_generic_to_global(src)));
}
__device__ __forceinline__ void ldsm4(uint32_t* r, uint32_t addr) {
    asm("ldmatrix.sync.aligned.m8n8.x4.shared.b16 {%0,%1,%2,%3}, [%4];"
        : "=r"(r[0]), "=r"(r[1]), "=r"(r[2]), "=r"(r[3]) : "r"(addr) : "memory");
}
__device__ __forceinline__ void mma16816(float* c, const uint32_t* a, const uint32_t* b) {
    asm("mma.sync.aligned.m16n8k16.row.col.f32.f16.f16.f32 "
        "{%0,%1,%2,%3}, {%4,%5,%6,%7}, {%8,%9}, {%0,%1,%2,%3};"
        : "+f"(c[0]), "+f"(c[1]), "+f"(c[2]), "+f"(c[3])
        : "r"(a[0]), "r"(a[1]), "r"(a[2]), "r"(a[3]), "r"(b[0]), "r"(b[1]));
}
__device__ __forceinline__ uint32_t h2u(__half2 h) {
    uint32_t u; __builtin_memcpy(&u, &h, 4); return u;
}
__device__ __forceinline__ void cvt_pair(float x, float y, uint32_t& hi, uint32_t& lo) {
    __half2 h = __floats2half2_rn(x, y);
    float2 g = __half22float2(h);
    __half2 l = __floats2half2_rn(x - g.x, y - g.y);
    hi = h2u(h); lo = h2u(l);
}
__device__ __forceinline__ float2 lds64(const char* smem, uint32_t off) {
    return *reinterpret_cast<const float2*>(smem + off);
}

// ---------------- prep: weights -> fp16 hi/lo + stat init ----------------
#define W_UNITS (N_TOT * HID / 8)   // 40960
#define W_BLOCKS (W_UNITS / 256)    // 160

__global__ void prep_w_kernel(const float* __restrict__ RW, const float* __restrict__ W1) {
    if (blockIdx.x == 0 && threadIdx.x < NEXP) {
        g_load[threadIdx.x] = 0.0f;
        if (threadIdx.x == 0) g_ent = 0.0f;
    }
    size_t u = (size_t)blockIdx.x * 256 + threadIdx.x;
    size_t e = u * 8;
    int row = (int)(e >> 10);
    const float* src = (row < NEXP) ? (RW + e) : (W1 + e - (size_t)NEXP * HID);
    float4 f0 = reinterpret_cast<const float4*>(src)[0];
    float4 f1 = reinterpret_cast<const float4*>(src)[1];
    uint32_t h0, l0, h1, l1, h2, l2, h3, l3;
    cvt_pair(f0.x, f0.y, h0, l0);
    cvt_pair(f0.z, f0.w, h1, l1);
    cvt_pair(f1.x, f1.y, h2, l2);
    cvt_pair(f1.z, f1.w, h3, l3);
    *reinterpret_cast<uint4*>(g_whi + e) = make_uint4(h0, h1, h2, h3);
    *reinterpret_cast<uint4*>(g_wlo + e) = make_uint4(l0, l1, l2, l3);
}

// ---------------- GEMM (occ 2) + fused epilogue + ticket finalize ----------------
__global__ void __launch_bounds__(THREADS, 2)
gemm_kernel(const float* __restrict__ X,
            const float* __restrict__ B1, const float* __restrict__ W2,
            const float* __restrict__ B2,
            float* __restrict__ logits, float* __restrict__ sel, float* __restrict__ wts,
            float* __restrict__ ovar, float* __restrict__ oent)
{
    extern __shared__ __align__(1024) char smem[];
    const uint32_t sbase = smem_u32(smem);
    const int tid = threadIdx.x;
    const int lane = tid & 31;
    const int wid = tid >> 5;
    const int wm = wid & 1;          // 2 m-groups * 32 rows
    const int wn = wid >> 1;         // 4 n-groups * 80 cols
    const int m0 = blockIdx.x * MT;

    float acc[2][10][4];
#pragma unroll
    for (int i = 0; i < 2; i++)
#pragma unroll
        for (int j = 0; j < 10; j++)
#pragma unroll
            for (int r = 0; r < 4; r++) acc[i][j][r] = 0.0f;

    uint32_t aL[2];
#pragma unroll
    for (int mt = 0; mt < 2; mt++) {
        int arow = wm * 32 + mt * 16 + (lane >> 2);
        aL[mt] = (uint32_t)arow * A_PITCH + (uint32_t)(lane & 3) * 8;
    }

    uint32_t bOff[5], bXor[5];
#pragma unroll
    for (int p = 0; p < 5; p++) {
        int n = wn * 80 + (p * 2 + ((lane >> 4) & 1)) * 8 + (lane & 7);
        bOff[p] = (uint32_t)n * 64;
        bXor[p] = ((uint32_t)n * 8) & 0x30;
    }
    const uint32_t bKB = ((lane >> 3) & 1) * 16;

    auto issue = [&](int c) {
        if (c < NCHUNK) {
            const uint32_t sb = sbase + (uint32_t)(c & 1) * ST_BYTES;
            const size_t k0 = (size_t)c * KC;
#pragma unroll
            for (int it = 0; it < 12; it++) {
                int u = tid + it * THREADS;
                if (u < 512) {
                    int r = u >> 3, g = u & 7;
                    const float* src = X + (size_t)(m0 + r) * HID + k0 + g * 4;
                    cp16(sb + (uint32_t)r * A_PITCH + (uint32_t)g * 16, src);
                } else {
                    int t = u - 512;
                    int v = t >= 1280;
                    int j = v ? t - 1280 : t;
                    int n = j >> 2, g = j & 3;
                    const __half* src = (v ? g_wlo : g_whi) + (size_t)n * HID + k0 + g * 8;
                    cp16(sb + (v ? B_LO_OFF : B_HI_OFF) +
                         ((uint32_t)n * 64 + (((uint32_t)g * 16) ^ (((uint32_t)n * 8) & 0x30))),
                         src);
                }
            }
        }
        asm volatile("cp.async.commit_group;");
    };

    issue(0);

    for (int c = 0; c < NCHUNK; c++) {
        asm volatile("cp.async.wait_group 0;");
        __syncthreads();
        issue(c + 1);

        const uint32_t stOff = (uint32_t)(c & 1) * ST_BYTES;
        const char* sA = smem + stOff;
        const uint32_t sb = sbase + stOff;
#pragma unroll
        for (int ks = 0; ks < 2; ks++) {
            const uint32_t kf = ks * 64;
            const uint32_t kb = ks * 32;
            uint32_t ah[2][4], al[2][4], bb[5][4];
#pragma unroll
            for (int mt = 0; mt < 2; mt++) {
                uint32_t base = aL[mt] + kf;
                float2 f00 = lds64(sA, base);
                float2 f10 = lds64(sA, base + 8 * A_PITCH);
                float2 f01 = lds64(sA, base + 32);
                float2 f11 = lds64(sA, base + 8 * A_PITCH + 32);
                cvt_pair(f00.x, f00.y, ah[mt][0], al[mt][0]);
                cvt_pair(f10.x, f10.y, ah[mt][1], al[mt][1]);
                cvt_pair(f01.x, f01.y, ah[mt][2], al[mt][2]);
                cvt_pair(f11.x, f11.y, ah[mt][3], al[mt][3]);
            }
#pragma unroll
            for (int p = 0; p < 5; p++)
                ldsm4(bb[p], sb + B_HI_OFF + bOff[p] + ((kb + bKB) ^ bXor[p]));
#pragma unroll
            for (int mt = 0; mt < 2; mt++)
#pragma unroll
                for (int p = 0; p < 5; p++) {
                    mma16816(acc[mt][p * 2 + 0], ah[mt], &bb[p][0]);
                    mma16816(acc[mt][p * 2 + 1], ah[mt], &bb[p][2]);
                }
#pragma unroll
            for (int mt = 0; mt < 2; mt++)
#pragma unroll
                for (int p = 0; p < 5; p++) {
                    mma16816(acc[mt][p * 2 + 0], al[mt], &bb[p][0]);
                    mma16816(acc[mt][p * 2 + 1], al[mt], &bb[p][2]);
                }
#pragma unroll
            for (int p = 0; p < 5; p++)
                ldsm4(bb[p], sb + B_LO_OFF + bOff[p] + ((kb + bKB) ^ bXor[p]));
#pragma unroll
            for (int mt = 0; mt < 2; mt++)
#pragma unroll
                for (int p = 0; p < 5; p++) {
                    mma16816(acc[mt][p * 2 + 0], ah[mt], &bb[p][0]);
                    mma16816(acc[mt][p * 2 + 1], ah[mt], &bb[p][2]);
                }
        }
    }

    // ---------------- fused epilogue ----------------
    float* s_log  = reinterpret_cast<float*>(smem);           // [64][68]
    float* s_u    = reinterpret_cast<float*>(smem + 17408);   // [64]
    float* s_load = s_u + 64;                                 // [64]
    float* s_ent  = s_load + NEXP;

    __syncthreads();
    if (tid < MT)   s_u[tid] = B2[0];
    if (tid < NEXP) s_load[tid] = 0.0f;
    if (tid == 0)   *s_ent = 0.0f;
    __syncthreads();

#pragma unroll
    for (int mt = 0; mt < 2; mt++) {
        float u0 = 0.0f, u1 = 0.0f;
        const int row0 = wm * 32 + mt * 16 + (lane >> 2);
#pragma unroll
        for (int nt = 0; nt < 10; nt++) {
            const int nb = wn * 80 + nt * 8 + (lane & 3) * 2;
            const bool is_logit = (wn == 0 && nt < 8);
#pragma unroll
            for (int r = 0; r < 4; r++) {
                const int n = nb + (r & 1);
                const float v = acc[mt][nt][r];
                if (is_logit) {
                    const int rl = row0 + ((r >= 2) ? 8 : 0);
                    s_log[rl * 68 + n] = v;
                } else {
                    const int h = n - 64;
                    const float hh = fmaxf(v + __ldg(B1 + h), 0.0f) * __ldg(W2 + h);
                    if (r < 2) u0 += hh; else u1 += hh;
                }
            }
        }
        u0 += __shfl_xor_sync(0xffffffffu, u0, 1);
        u0 += __shfl_xor_sync(0xffffffffu, u0, 2);
        u1 += __shfl_xor_sync(0xffffffffu, u1, 1);
        u1 += __shfl_xor_sync(0xffffffffu, u1, 2);
        if ((lane & 3) == 0) {
            atomicAdd(&s_u[row0], u0);
            atomicAdd(&s_u[row0 + 8], u1);
        }
    }
    __syncthreads();

    // logits -> global
#pragma unroll
    for (int it = 0; it < 4; it++) {
        int t = tid + it * THREADS;
        int r = t >> 4, c4 = t & 15;
        float4 v = *reinterpret_cast<const float4*>(s_log + r * 68 + c4 * 4);
        *reinterpret_cast<float4*>(logits + (size_t)(m0 + r) * NEXP + c4 * 4) = v;
    }

    // softmax stats: 4 lanes per token x 16 experts
    {
        const int t = tid >> 2, q = tid & 3;
        const float* row = s_log + t * 68 + q * 16;
        float xs[16];
        float mx = -INFINITY;
#pragma unroll
        for (int i = 0; i < 16; i++) { xs[i] = row[i]; mx = fmaxf(mx, xs[i]); }
        mx = fmaxf(mx, __shfl_xor_sync(0xffffffffu, mx, 1));
        mx = fmaxf(mx, __shfl_xor_sync(0xffffffffu, mx, 2));
        float se = 0.0f, sc = 0.0f;
#pragma unroll
        for (int i = 0; i < 16; i++) {
            float d = xs[i] - mx;
            float e = __expf(d);
            se += e;
            sc = fmaf(e, d, sc);
            xs[i] = e;
        }
        se += __shfl_xor_sync(0xffffffffu, se, 1);
        se += __shfl_xor_sync(0xffffffffu, se, 2);
        sc += __shfl_xor_sync(0xffffffffu, sc, 1);
        sc += __shfl_xor_sync(0xffffffffu, sc, 2);
        const float inv = 1.0f / se;
#pragma unroll
        for (int i = 0; i < 16; i++) {
            float p = xs[i] * inv;
            p += __shfl_xor_sync(0xffffffffu, p, 4);
            p += __shfl_xor_sync(0xffffffffu, p, 8);
            p += __shfl_xor_sync(0xffffffffu, p, 16);
            xs[i] = p;
        }
        if (lane < 4) {
#pragma unroll
            for (int i = 0; i < 16; i++) atomicAdd(&s_load[lane * 16 + i], xs[i]);
        }
        float ent = (q == 0) ? (__logf(se) - sc * inv) : 0.0f;
        ent += __shfl_xor_sync(0xffffffffu, ent, 1);
        ent += __shfl_xor_sync(0xffffffffu, ent, 2);
        ent += __shfl_xor_sync(0xffffffffu, ent, 4);
        ent += __shfl_xor_sync(0xffffffffu, ent, 8);
        ent += __shfl_xor_sync(0xffffffffu, ent, 16);
        if (lane == 0) atomicAdd(s_ent, ent);
    }
    __syncthreads();

    // top-k + weights (tid<64); stats flush (tid in [64,129)) with release fence
    if (tid < MT) {
        const int m = m0 + tid;
        const float* row = s_log + tid * 68;

        float v0 = -INFINITY, v1 = -INFINITY, v2 = -INFINITY, v3 = -INFINITY;
        int i0 = 0, i1 = 0, i2 = 0, i3 = 0;
#pragma unroll
        for (int j = 0; j < NEXP; j++) {
            float x = row[j];
            if (x > v3) {
                if (x > v0)      { v3=v2;i3=i2; v2=v1;i2=i1; v1=v0;i1=i0; v0=x;i0=j; }
                else if (x > v1) { v3=v2;i3=i2; v2=v1;i2=i1; v1=x;i1=j; }
                else if (x > v2) { v3=v2;i3=i2; v2=x;i2=j; }
                else             { v3=x;i3=j; }
            }
        }
        float u = s_u[tid];
        float cplx = 1.0f / (1.0f + expf(-u));
        int kk = (cplx > 0.5f) ? 4 : 1;
        float e0 = 1.0f;
        float e1 = (kk > 1) ? expf(v1 - v0) : 0.0f;
        float e2 = (kk > 2) ? expf(v2 - v0) : 0.0f;
        float e3 = (kk > 3) ? expf(v3 - v0) : 0.0f;
        float wi = 1.0f / (e0 + e1 + e2 + e3);

        *reinterpret_cast<float4*>(sel + (size_t)m * 4) =
            make_float4((float)i0, (float)((kk > 1) ? i1 : 0),
                        (float)((kk > 2) ? i2 : 0), (float)((kk > 3) ? i3 : 0));
        *reinterpret_cast<float4*>(wts + (size_t)m * 4) =
            make_float4(e0 * wi, e1 * wi, e2 * wi, e3 * wi);
    } else if (tid < MT + NEXP) {
        atomicAdd(&g_load[tid - MT], s_load[tid - MT]);
        __threadfence();   // release this thread's stat atomic before ticket
    } else if (tid == MT + NEXP) {
        atomicAdd(&g_ent, *s_ent);
        __threadfence();
    }
    __syncthreads();

    // ticket: last CTA finalizes var/entropy (self-resetting for graph replay)
    if (tid == 0) {
        __threadfence();
        int t = atomicAdd(&g_ticket, 1);
        if (t == NCTAS - 1) {
            float xs[NEXP];
            float mean = 0.0f;
            for (int e = 0; e < NEXP; e++) {
                xs[e] = atomicAdd(&g_load[e], 0.0f) * (1.0f / N_TOK);  // coherent read
                mean += xs[e];
            }
            mean *= (1.0f / NEXP);
            float var = 0.0f;
            for (int e = 0; e < NEXP; e++) { float d = xs[e] - mean; var += d * d; }
            ovar[0] = var * (1.0f / (NEXP - 1));
            oent[0] = atomicAdd(&g_ent, 0.0f) * (1.0f / N_TOK);
            atomicExch(&g_ticket, 0);   // reset for next replay
        }
    }
}

// ---------------- launch ----------------
extern "C" void kernel_launch(void* const* d_in, const int* in_sizes, int n_in,
                              void* d_out, int out_size) {
    const float* X  = (const float*)d_in[0];
    const float* RW = (const float*)d_in[1];
    const float* W1 = (const float*)d_in[2];
    const float* B1 = (const float*)d_in[3];
    const float* W2 = (const float*)d_in[4];
    const float* B2 = (const float*)d_in[5];

    float* out    = (float*)d_out;
    float* logits = out;
    float* sel    = logits + (size_t)N_TOK * NEXP;
    float* wts    = sel + (size_t)N_TOK * 4;
    float* ovar   = wts + (size_t)N_TOK * 4;
    float* oent   = ovar + 1;

    cudaFuncSetAttribute(gemm_kernel, cudaFuncAttributeMaxDynamicSharedMemorySize, SMEM_TOTAL);

    prep_w_kernel<<<W_BLOCKS, 256>>>(RW, W1);
    gemm_kernel<<<NCTAS, THREADS, SMEM_TOTAL>>>(X, B1, W2, B2, logits, sel, wts, ovar, oent);
}